// round 15
// baseline (speedup 1.0000x reference)
#include <cuda_runtime.h>
#include <cuda_bf16.h>

// Table-batched EmbeddingBag forward (SUM pooling).
// T=8 tables, B=8192 batch, D=128 dim, ROWS=200000 rows/table.
// indices: [nnz] int32, offsets: [T*B+1] int32, weights: flat
// [T*ROWS*D] float32. out: [B, T*D] float32.
//
// One warp per bag per pass; lane l owns one float4 of the D=128 row
// (512B fully-coalesced gather per row). Combination of the two
// measured-good components from the 8-variant series:
//  - R13 body: hoisted per-warp table base + 32-bit within-table
//    offsets (shortest index->address->LDG chain; DRAM 76.9%).
//  - R9 grid: persistent single-wave launch (148x8 CTAs, occ 93.9%),
//    eliminating ~6 wave transitions + tail of the 8192-CTA launch.
// Everything else (pipelining, int4 indices, smem staging, cache
// hints) measured neutral-to-regressive and is deliberately absent.

#ifndef EMB_T
#define EMB_T 8
#define EMB_B 8192
#define EMB_D 128
#define EMB_ROWS 200000
#endif

#define D4 (EMB_D / 4)          // float4 per row = 32
#define NUM_SMS 148
#define BLOCKS_PER_SM 8

__global__ __launch_bounds__(256, 8) void emb_bag_sum_kernel(
    const int* __restrict__ indices,
    const int* __restrict__ offsets,
    const float4* __restrict__ weights4,   // weights viewed as float4
    float4* __restrict__ out4,             // out viewed as float4
    int n_bags)
{
    const int lane        = threadIdx.x & 31;
    const int warp_global = (blockIdx.x * blockDim.x + threadIdx.x) >> 5;
    const int warp_stride = (gridDim.x * blockDim.x) >> 5;

    for (int bag = warp_global; bag < n_bags; bag += warp_stride) {
        const int feature = bag / EMB_B;        // table id
        const int b       = bag - feature * EMB_B;

        const int start = __ldg(offsets + bag);
        const int end   = __ldg(offsets + bag + 1);

        // Per-warp base: table start + this lane's float4 within the
        // row. Within-table offsets (row*32 float4, max 6.4M) are 32-bit.
        const float4* __restrict__ tbl =
            weights4 + (size_t)feature * EMB_ROWS * D4 + lane;

        float4 acc = make_float4(0.f, 0.f, 0.f, 0.f);

        #pragma unroll 4
        for (int j = start; j < end; ++j) {
            const unsigned row = (unsigned)__ldg(indices + j);
            const float4 v = __ldg(tbl + row * (unsigned)D4);
            acc.x += v.x; acc.y += v.y; acc.z += v.z; acc.w += v.w;
        }

        const size_t o = (size_t)b * (EMB_T * D4)
                       + (size_t)feature * D4 + lane;
        out4[o] = acc;
    }
}

extern "C" void kernel_launch(void* const* d_in, const int* in_sizes, int n_in,
                              void* d_out, int out_size)
{
    const int*   indices = (const int*)d_in[0];
    const int*   offsets = (const int*)d_in[1];
    const float* weights = (const float*)d_in[2];

    const int n_bags = in_sizes[1] - 1;      // T*B
    int blocks = NUM_SMS * BLOCKS_PER_SM;    // one resident wave
    const int max_blocks = (n_bags + 7) / 8; // never launch idle blocks
    if (blocks > max_blocks) blocks = max_blocks;

    emb_bag_sum_kernel<<<blocks, 256>>>(
        indices, offsets,
        (const float4*)weights, (float4*)d_out, n_bags);
}

// round 16
// speedup vs baseline: 1.0742x; 1.0742x over previous
#include <cuda_runtime.h>
#include <cuda_bf16.h>

// Table-batched EmbeddingBag forward (SUM pooling).
// T=8 tables, B=8192 batch, D=128 dim, ROWS=200000 rows/table.
// indices: [nnz] int32, offsets: [T*B+1] int32, weights: flat
// [T*ROWS*D] float32. out: [B, T*D] float32.
//
// One warp per bag. Lane l owns floats [4l, 4l+4) of the D=128 row
// (one float4); each row gather is a fully-coalesced 512B read.
// Empirical optimum across 9 measured variants (series best:
// 81.9us bench / 79.9us ncu, DRAM 76.9% = 6.29 TB/s):
//  - simple dependent loop, scalar broadcast index loads (4
//    independent in flight via unroll), two no-op-free accumulators
//  - hoisted per-warp table base + 32-bit within-table offsets
//    (table = 102MB < 4GB) -> shortest index->address->LDG chain
//  - plain 8192-CTA launch (persistent grid measured worse twice;
//    work-stealing hides wave transitions)
//  - no pipelining / int4 indices / smem staging / cache hints —
//    each measured neutral-to-regressive.
// Traffic is at the distinct-row floor (L2 harvests duplicates);
// remaining DRAM headroom is random-512B-row activation cost.

#ifndef EMB_T
#define EMB_T 8
#define EMB_B 8192
#define EMB_D 128
#define EMB_ROWS 200000
#endif

#define D4 (EMB_D / 4)   // float4 per row = 32

__global__ __launch_bounds__(256) void emb_bag_sum_kernel(
    const int* __restrict__ indices,
    const int* __restrict__ offsets,
    const float4* __restrict__ weights4,   // weights viewed as float4
    float4* __restrict__ out4,             // out viewed as float4
    int n_bags)
{
    const int warp_id = (blockIdx.x * blockDim.x + threadIdx.x) >> 5;
    const int lane    = threadIdx.x & 31;
    if (warp_id >= n_bags) return;

    const int bag     = warp_id;
    const int feature = bag / EMB_B;        // table id
    const int b       = bag - feature * EMB_B;

    const int start = __ldg(offsets + bag);
    const int end   = __ldg(offsets + bag + 1);

    // Per-warp base: table start + this lane's float4 within the row.
    // Within-table offsets (row * 32 float4, max 6.4M) fit in 32 bits.
    const float4* __restrict__ tbl =
        weights4 + (size_t)feature * EMB_ROWS * D4 + lane;

    float4 acc = make_float4(0.f, 0.f, 0.f, 0.f);

    #pragma unroll 4
    for (int j = start; j < end; ++j) {
        const unsigned row = (unsigned)__ldg(indices + j);
        const float4 v = __ldg(tbl + row * (unsigned)D4);
        acc.x += v.x; acc.y += v.y; acc.z += v.z; acc.w += v.w;
    }

    const size_t o = (size_t)b * (EMB_T * D4) + (size_t)feature * D4 + lane;
    out4[o] = acc;
}

extern "C" void kernel_launch(void* const* d_in, const int* in_sizes, int n_in,
                              void* d_out, int out_size)
{
    const int*   indices = (const int*)d_in[0];
    const int*   offsets = (const int*)d_in[1];
    const float* weights = (const float*)d_in[2];

    const int n_bags = in_sizes[1] - 1;         // T*B
    const int warps_per_block = 256 / 32;       // 8
    const int blocks = (n_bags + warps_per_block - 1) / warps_per_block;

    emb_bag_sum_kernel<<<blocks, 256>>>(
        indices, offsets,
        (const float4*)weights, (float4*)d_out, n_bags);
}